// round 14
// baseline (speedup 1.0000x reference)
#include <cuda_runtime.h>
#include <cuda_fp16.h>
#include <cuda_bf16.h>
#include <stdint.h>
#include <math.h>

#define BB 64
#define TT 2048
#define FF 64
#define HH 160
#define GG 480            // 3*H
#define BT (BB*TT)        // 131072

typedef unsigned long long ull;
typedef unsigned int u32;

// ---------------- scratch (device globals; allocation-free) ----------------
__device__ float g_z  [BT*FF];
__device__ float g_xg1[BT*GG];
__device__ float g_h1 [BT*HH];
__device__ float g_xg2[BT*GG];
__device__ float g_h2T[BB*HH];

// ---------------- packed f32x2 helpers (K2/K4 only) ----------------
__device__ __forceinline__ ull fma2(ull a, ull b, ull c) {
    ull d;
    asm("fma.rn.f32x2 %0, %1, %2, %3;" : "=l"(d) : "l"(a), "l"(b), "l"(c));
    return d;
}
__device__ __forceinline__ float f2sum(ull u) {
    float x, y;
    asm("mov.b64 {%0,%1}, %2;" : "=f"(x), "=f"(y) : "l"(u));
    return x + y;
}
__device__ __forceinline__ ull fpack(float lo, float hi) {
    ull p;
    asm("mov.b64 %0, {%1,%2};" : "=l"(p) : "f"(lo), "f"(hi));
    return p;
}

__device__ __forceinline__ float tanha(float x) {
    float y;
    asm("tanh.approx.f32 %0, %1;" : "=f"(y) : "f"(x));
    return y;
}
__device__ __forceinline__ float sigap(float x) {
    return fmaf(0.5f, tanha(0.5f * x), 0.5f);
}

// ============================================================================
// K1: dilated conv (k=3, dil=2, pad=2) + batchnorm(inference) + exact GELU
// ============================================================================
#define K1_TT 32
__global__ void k1_conv(const float* __restrict__ x, const float* __restrict__ mix_w,
                        const float* __restrict__ bn_g, const float* __restrict__ bn_b,
                        const float* __restrict__ bn_m, const float* __restrict__ bn_v)
{
    extern __shared__ float sm[];
    float* ws = sm;                    // [3][64][64] : ws[(k*64+i)*64+f]
    float* xs = sm + 3*64*64;          // [36][64]
    const int b  = blockIdx.y;
    const int t0 = blockIdx.x * K1_TT;
    const int tid = threadIdx.x;       // 256 threads

    for (int idx = tid; idx < FF*FF*3; idx += 256) {
        int f = idx / 192; int rem = idx - f*192; int i = rem / 3; int k = rem - i*3;
        ws[(k*64 + i)*64 + f] = mix_w[idx];
    }
    for (int idx = tid; idx < 36*64; idx += 256) {
        int r = idx >> 6; int i = idx & 63;
        int t = t0 - 2 + r;
        xs[idx] = (t >= 0 && t < TT) ? x[((b*TT) + t)*64 + i] : 0.f;
    }
    __syncthreads();

    const int f  = tid & 63;
    const int tg = tid >> 6;
    const float sc = bn_g[f] * rsqrtf(bn_v[f] + 1e-5f);
    const float sh = bn_b[f] - bn_m[f] * sc;
    const float4* xs4 = (const float4*)xs;

    for (int m = 0; m < 8; m++) {
        int tl = tg + 4*m;
        float acc = 0.f;
        #pragma unroll
        for (int k = 0; k < 3; k++) {
            int r = tl + 2*k;
            const float* wk = ws + k*4096 + f;
            #pragma unroll
            for (int i4 = 0; i4 < 16; i4++) {
                float4 xv = xs4[r*16 + i4];
                acc += xv.x * wk[(i4*4 + 0)*64];
                acc += xv.y * wk[(i4*4 + 1)*64];
                acc += xv.z * wk[(i4*4 + 2)*64];
                acc += xv.w * wk[(i4*4 + 3)*64];
            }
        }
        float y  = acc * sc + sh;
        float zz = 0.5f * y * (1.f + erff(y * 0.70710678118654752f));
        g_z[((b*TT) + (t0 + tl))*64 + f] = zz;
    }
}
#define SMEM1 ((3*64*64 + 36*64)*4)

// ============================================================================
// K2: xg1 = g_z @ w_ih1^T + b_ih1      [BT,64] @ [64,480]  — all-reg, f32x2
// ============================================================================
__global__ __launch_bounds__(480) void k2_xproj(const float* __restrict__ w_ih,
                                                const float* __restrict__ b_ih)
{
    extern __shared__ float zs[];      // [64][64]
    const int c = threadIdx.x;

    ull wr[32];
    #pragma unroll
    for (int i = 0; i < 16; i++) {
        ulonglong2 v = *reinterpret_cast<const ulonglong2*>(w_ih + c*64 + 4*i);
        wr[2*i] = v.x; wr[2*i+1] = v.y;
    }
    const float bias = b_ih[c];

    const int start = blockIdx.x * 896;          // 14 tiles of 64 rows
    for (int tile = 0; tile < 14; tile++) {
        int r0 = start + tile*64;
        if (r0 >= BT) break;
        __syncthreads();
        for (int idx = c; idx < 64*16; idx += 480)
            ((float4*)zs)[idx] = ((const float4*)(g_z + (size_t)r0*64))[idx];
        __syncthreads();
        for (int r = 0; r < 64; r += 2) {
            ull a0 = 0ull, a1 = 0ull, b0 = 0ull, b1 = 0ull;
            const float* z0 = zs + r*64;
            const float* z1 = zs + r*64 + 64;
            #pragma unroll
            for (int i = 0; i < 16; i++) {
                ulonglong2 h0 = *reinterpret_cast<const ulonglong2*>(z0 + 4*i);
                ulonglong2 h1 = *reinterpret_cast<const ulonglong2*>(z1 + 4*i);
                a0 = fma2(h0.x, wr[2*i],   a0);
                a1 = fma2(h0.y, wr[2*i+1], a1);
                b0 = fma2(h1.x, wr[2*i],   b0);
                b1 = fma2(h1.y, wr[2*i+1], b1);
            }
            g_xg1[(size_t)(r0 + r    )*GG + c] = bias + f2sum(a0) + f2sum(a1);
            g_xg1[(size_t)(r0 + r + 1)*GG + c] = bias + f2sum(b0) + f2sum(b1);
        }
    }
}
#define SMEM2 (64*64*4)

// ============================================================================
// K4: xg2 = g_h1 @ w_ih2^T + b_ih2     [BT,160] @ [160,480]
//     hybrid: k<80 in regs (f32x2), k>=80 in smem as ull pairs [q][480+1]
// ============================================================================
#define K4_WS 481
__global__ __launch_bounds__(480) void k4_xproj160(const float* __restrict__ w_ih,
                                                   const float* __restrict__ b_ih)
{
    extern __shared__ __align__(16) char smraw[];
    ull*   wsm = (ull*)smraw;                      // [40][481] k-pairs for k>=80
    float* zs  = (float*)(smraw + 40*K4_WS*8);     // [16][160]
    const int c = threadIdx.x;

    for (int idx = c; idx < 480*40; idx += 480) {
        int cc = idx / 40; int q = idx - cc*40;
        float lo = w_ih[cc*160 + 80 + 2*q];
        float hi = w_ih[cc*160 + 81 + 2*q];
        wsm[q*K4_WS + cc] = fpack(lo, hi);
    }
    ull wr[40];
    #pragma unroll
    for (int i = 0; i < 20; i++) {
        ulonglong2 v = *reinterpret_cast<const ulonglong2*>(w_ih + c*160 + 4*i);
        wr[2*i] = v.x; wr[2*i+1] = v.y;
    }
    const float bias = b_ih[c];

    const int start = blockIdx.x * 896;            // 56 tiles of 16 rows
    for (int tile = 0; tile < 56; tile++) {
        int r0 = start + tile*16;
        if (r0 >= BT) break;
        __syncthreads();
        for (int idx = c; idx < 16*40; idx += 480)
            ((float4*)zs)[idx] = ((const float4*)(g_h1 + (size_t)r0*160))[idx];
        __syncthreads();
        for (int rg = 0; rg < 16; rg += 4) {
            const float* z0 = zs + (rg+0)*160;
            const float* z1 = zs + (rg+1)*160;
            const float* z2 = zs + (rg+2)*160;
            const float* z3 = zs + (rg+3)*160;
            ull a0 = 0ull, a1 = 0ull, a2 = 0ull, a3 = 0ull;
            #pragma unroll
            for (int i = 0; i < 20; i++) {
                ull wa = wr[2*i], wb = wr[2*i+1];
                ulonglong2 h;
                h = *reinterpret_cast<const ulonglong2*>(z0 + 4*i);
                a0 = fma2(h.x, wa, a0); a0 = fma2(h.y, wb, a0);
                h = *reinterpret_cast<const ulonglong2*>(z1 + 4*i);
                a1 = fma2(h.x, wa, a1); a1 = fma2(h.y, wb, a1);
                h = *reinterpret_cast<const ulonglong2*>(z2 + 4*i);
                a2 = fma2(h.x, wa, a2); a2 = fma2(h.y, wb, a2);
                h = *reinterpret_cast<const ulonglong2*>(z3 + 4*i);
                a3 = fma2(h.x, wa, a3); a3 = fma2(h.y, wb, a3);
            }
            #pragma unroll
            for (int i = 0; i < 20; i++) {
                ull wa = wsm[(2*i  )*K4_WS + c];
                ull wb = wsm[(2*i+1)*K4_WS + c];
                ulonglong2 h;
                h = *reinterpret_cast<const ulonglong2*>(z0 + 80 + 4*i);
                a0 = fma2(h.x, wa, a0); a0 = fma2(h.y, wb, a0);
                h = *reinterpret_cast<const ulonglong2*>(z1 + 80 + 4*i);
                a1 = fma2(h.x, wa, a1); a1 = fma2(h.y, wb, a1);
                h = *reinterpret_cast<const ulonglong2*>(z2 + 80 + 4*i);
                a2 = fma2(h.x, wa, a2); a2 = fma2(h.y, wb, a2);
                h = *reinterpret_cast<const ulonglong2*>(z3 + 80 + 4*i);
                a3 = fma2(h.x, wa, a3); a3 = fma2(h.y, wb, a3);
            }
            g_xg2[(size_t)(r0 + rg    )*GG + c] = bias + f2sum(a0);
            g_xg2[(size_t)(r0 + rg + 1)*GG + c] = bias + f2sum(a1);
            g_xg2[(size_t)(r0 + rg + 2)*GG + c] = bias + f2sum(a2);
            g_xg2[(size_t)(r0 + rg + 3)*GG + c] = bias + f2sum(a3);
        }
    }
}
#define SMEM4 (40*K4_WS*8 + 16*160*4)

// ============================================================================
// K3: GRU via tensor cores. 16 batches per CTA, grid=4.
//     Per step: hp[16,480] = h16[16,160] @ W16^T via mma.sync m16n8k16
//     (fp16 inputs, fp32 accumulate). W16 fp16 resident in smem.
//     h kept in fp32 (h32) for the recurrence; fp16 copy only feeds the MMA.
//     15 warps, warp w owns n-columns [32w, 32w+32).
// ============================================================================
#define NB   16            // batches per CTA
#define WST  168           // fp16 row stride (weights & h) -> conflict-free
#define HPS  482           // hp row stride (f32)
#define OFF_W16 0
#define OFF_H16 (GG*WST*2)
#define OFF_HP  (OFF_H16 + NB*WST*2)
#define OFF_H32 (OFF_HP + NB*HPS*4)
#define SMEMG   (OFF_H32 + NB*HH*4)     // 207744 B < 227KB cap

__device__ __forceinline__ void mma16816(float c[4], u32 a0, u32 a1, u32 a2, u32 a3,
                                         u32 b0, u32 b1) {
    asm("mma.sync.aligned.m16n8k16.row.col.f32.f16.f16.f32 "
        "{%0,%1,%2,%3}, {%4,%5,%6,%7}, {%8,%9}, {%0,%1,%2,%3};"
        : "+f"(c[0]), "+f"(c[1]), "+f"(c[2]), "+f"(c[3])
        : "r"(a0), "r"(a1), "r"(a2), "r"(a3), "r"(b0), "r"(b1));
}

__global__ __launch_bounds__(480, 1) void k_gru_mma(const float* __restrict__ w_hh,
                                                    const float* __restrict__ b_hh,
                                                    int which)
{
    extern __shared__ __align__(16) char smg[];
    __half* W16 = (__half*)(smg + OFF_W16);   // [480][WST]
    __half* h16 = (__half*)(smg + OFF_H16);   // [16][WST]
    float*  hp  = (float*) (smg + OFF_HP);    // [16][HPS]
    float*  h32 = (float*) (smg + OFF_H32);   // [16][160]

    const int tid = threadIdx.x;
    const int b0  = blockIdx.x * NB;

    // stage W16 (coalesced read, one-time)
    for (int idx = tid; idx < GG*HH; idx += 480) {
        int r = idx / HH; int k = idx - r*HH;
        W16[r*WST + k] = __float2half(w_hh[idx]);
    }
    for (int idx = tid; idx < NB*WST; idx += 480) h16[idx] = __float2half(0.f);
    for (int idx = tid; idx < NB*HH;  idx += 480) h32[idx] = 0.f;
    __syncthreads();

    const int w    = tid >> 5;
    const int l    = tid & 31;
    const int grp  = l >> 2;        // 0..7
    const int tid4 = l & 3;         // 0..3
    const int n0w  = w * 32;

    // gate-thread mapping: unit ui = tid%160, batches q = q0 + 3j
    const int ui = tid % HH;
    const int q0 = tid / HH;        // 0..2
    const float bbr = b_hh[ui];
    const float bbz = b_hh[HH + ui];
    const float bbn = b_hh[2*HH + ui];

    const float* __restrict__ xg = which ? g_xg2 : g_xg1;

    // prefetch xg for t=0
    float pxr[6], pxz[6], pxn[6];
    #pragma unroll
    for (int j = 0; j < 6; j++) {
        int q = q0 + 3*j; if (q > NB-1) q = NB-1;
        const float* p = xg + (size_t)(b0 + q) * TT * GG;
        pxr[j] = p[ui]; pxz[j] = p[HH + ui]; pxn[j] = p[2*HH + ui];
    }

    for (int t = 0; t < TT; t++) {
        // ---------------- MMA phase: hp = h16 @ W16^T ----------------
        float c0[4], c1[4], c2[4], c3[4];
        #pragma unroll
        for (int k = 0; k < 4; k++) { c0[k]=0.f; c1[k]=0.f; c2[k]=0.f; c3[k]=0.f; }

        #pragma unroll
        for (int kc = 0; kc < 10; kc++) {
            const int kb = kc*16 + 2*tid4;
            u32 a0 = *(const u32*)&h16[(grp    )*WST + kb    ];
            u32 a1 = *(const u32*)&h16[(grp + 8)*WST + kb    ];
            u32 a2 = *(const u32*)&h16[(grp    )*WST + kb + 8];
            u32 a3 = *(const u32*)&h16[(grp + 8)*WST + kb + 8];
            {
                int nr = (n0w + 0*8 + grp)*WST;
                mma16816(c0, a0,a1,a2,a3, *(const u32*)&W16[nr + kb], *(const u32*)&W16[nr + kb + 8]);
            }
            {
                int nr = (n0w + 1*8 + grp)*WST;
                mma16816(c1, a0,a1,a2,a3, *(const u32*)&W16[nr + kb], *(const u32*)&W16[nr + kb + 8]);
            }
            {
                int nr = (n0w + 2*8 + grp)*WST;
                mma16816(c2, a0,a1,a2,a3, *(const u32*)&W16[nr + kb], *(const u32*)&W16[nr + kb + 8]);
            }
            {
                int nr = (n0w + 3*8 + grp)*WST;
                mma16816(c3, a0,a1,a2,a3, *(const u32*)&W16[nr + kb], *(const u32*)&W16[nr + kb + 8]);
            }
        }
        // store D frags -> hp
        {
            int col0 = n0w + 0*8 + 2*tid4;
            *(float2*)&hp[(grp  )*HPS + col0] = make_float2(c0[0], c0[1]);
            *(float2*)&hp[(grp+8)*HPS + col0] = make_float2(c0[2], c0[3]);
            int col1 = n0w + 1*8 + 2*tid4;
            *(float2*)&hp[(grp  )*HPS + col1] = make_float2(c1[0], c1[1]);
            *(float2*)&hp[(grp+8)*HPS + col1] = make_float2(c1[2], c1[3]);
            int col2 = n0w + 2*8 + 2*tid4;
            *(float2*)&hp[(grp  )*HPS + col2] = make_float2(c2[0], c2[1]);
            *(float2*)&hp[(grp+8)*HPS + col2] = make_float2(c2[2], c2[3]);
            int col3 = n0w + 3*8 + 2*tid4;
            *(float2*)&hp[(grp  )*HPS + col3] = make_float2(c3[0], c3[1]);
            *(float2*)&hp[(grp+8)*HPS + col3] = make_float2(c3[2], c3[3]);
        }
        __syncthreads();

        // ---------------- gate phase ----------------
        float nxr[6] = {0,0,0,0,0,0}, nxz[6] = {0,0,0,0,0,0}, nxn[6] = {0,0,0,0,0,0};
        if (t + 1 < TT) {
            #pragma unroll
            for (int j = 0; j < 6; j++) {
                int q = q0 + 3*j; if (q > NB-1) q = NB-1;
                const float* p = xg + ((size_t)(b0 + q) * TT + (t+1)) * GG;
                nxr[j] = p[ui]; nxz[j] = p[HH + ui]; nxn[j] = p[2*HH + ui];
            }
        }
        #pragma unroll
        for (int j = 0; j < 6; j++) {
            int q = q0 + 3*j;
            bool valid = (q < NB);
            int qc = valid ? q : NB-1;
            float hpr = hp[qc*HPS + ui];
            float hpz = hp[qc*HPS + HH + ui];
            float hpn = hp[qc*HPS + 2*HH + ui];
            float r  = sigap(pxr[j] + bbr + hpr);
            float z  = sigap(pxz[j] + bbz + hpz);
            float nn = tanha(pxn[j] + r * (hpn + bbn));
            float hold = h32[qc*HH + ui];
            float hnew = (1.f - z) * nn + z * hold;
            if (valid) {
                h32[qc*HH + ui] = hnew;
                h16[qc*WST + ui] = __float2half(hnew);
                if (!which) g_h1[((size_t)(b0 + qc)*TT + t)*HH + ui] = hnew;
            }
            pxr[j] = nxr[j]; pxz[j] = nxz[j]; pxn[j] = nxn[j];
        }
        __syncthreads();
    }

    if (which) {
        for (int idx = tid; idx < NB*HH; idx += 480)
            g_h2T[(b0 + idx/HH)*HH + (idx % HH)] = h32[idx];
    }
}

// ============================================================================
// K5: head
// ============================================================================
__global__ void k_head(const float* __restrict__ hw1, const float* __restrict__ hb1,
                       const float* __restrict__ hw2, const float* __restrict__ hb2,
                       float* __restrict__ out)
{
    __shared__ float q[80];
    const int b = blockIdx.x;
    const int j = threadIdx.x;
    const float* h = g_h2T + b*HH;
    if (j < 80) {
        float acc = hb1[j];
        #pragma unroll 4
        for (int k = 0; k < 160; k++) acc += h[k] * hw1[j*160 + k];
        q[j] = 0.5f * acc * (1.f + erff(acc * 0.70710678118654752f));
    }
    __syncthreads();
    if (j < 2) {
        float o = hb2[j];
        #pragma unroll 4
        for (int k = 0; k < 80; k++) o += q[k] * hw2[j*80 + k];
        out[b*2 + j] = o;
    }
}

// ============================================================================
extern "C" void kernel_launch(void* const* d_in, const int* in_sizes, int n_in,
                              void* d_out, int out_size)
{
    const float* x     = (const float*)d_in[0];
    const float* mix_w = (const float*)d_in[1];
    const float* bn_g  = (const float*)d_in[2];
    const float* bn_b  = (const float*)d_in[3];
    const float* bn_m  = (const float*)d_in[4];
    const float* bn_v  = (const float*)d_in[5];
    const float* w_ih1 = (const float*)d_in[6];
    const float* w_hh1 = (const float*)d_in[7];
    const float* b_ih1 = (const float*)d_in[8];
    const float* b_hh1 = (const float*)d_in[9];
    const float* w_ih2 = (const float*)d_in[10];
    const float* w_hh2 = (const float*)d_in[11];
    const float* b_ih2 = (const float*)d_in[12];
    const float* b_hh2 = (const float*)d_in[13];
    const float* hw1   = (const float*)d_in[14];
    const float* hb1   = (const float*)d_in[15];
    const float* hw2   = (const float*)d_in[16];
    const float* hb2   = (const float*)d_in[17];
    float* out = (float*)d_out;

    cudaFuncSetAttribute(k1_conv,     cudaFuncAttributeMaxDynamicSharedMemorySize, SMEM1);
    cudaFuncSetAttribute(k2_xproj,    cudaFuncAttributeMaxDynamicSharedMemorySize, SMEM2);
    cudaFuncSetAttribute(k4_xproj160, cudaFuncAttributeMaxDynamicSharedMemorySize, SMEM4);
    cudaFuncSetAttribute(k_gru_mma,   cudaFuncAttributeMaxDynamicSharedMemorySize, SMEMG);

    k1_conv<<<dim3(TT/K1_TT, BB), 256, SMEM1>>>(x, mix_w, bn_g, bn_b, bn_m, bn_v);
    k2_xproj<<<148, 480, SMEM2>>>(w_ih1, b_ih1);
    k_gru_mma<<<BB/NB, 480, SMEMG>>>(w_hh1, b_hh1, 0);
    k4_xproj160<<<148, 480, SMEM4>>>(w_ih2, b_ih2);
    k_gru_mma<<<BB/NB, 480, SMEMG>>>(w_hh2, b_hh2, 1);
    k_head<<<BB, 128>>>(hw1, hb1, hw2, hb2, out);
}

// round 16
// speedup vs baseline: 1.2149x; 1.2149x over previous
#include <cuda_runtime.h>
#include <cuda_fp16.h>
#include <stdint.h>
#include <math.h>

#define BB 64
#define TT 2048
#define FF 64
#define HH 160
#define GG 480            // 3*H
#define BT (BB*TT)        // 131072

typedef unsigned long long ull;
typedef unsigned int u32;

// ---------------- scratch (device globals; allocation-free) ----------------
__device__ float g_z  [BT*FF];
__device__ float g_xg1[BT*GG];
__device__ float g_h1 [BT*HH];
__device__ float g_xg2[BT*GG];
__device__ float g_h2T[BB*HH];

// ---------------- packed f32x2 helpers (K2/K4 only) ----------------
__device__ __forceinline__ ull fma2(ull a, ull b, ull c) {
    ull d;
    asm("fma.rn.f32x2 %0, %1, %2, %3;" : "=l"(d) : "l"(a), "l"(b), "l"(c));
    return d;
}
__device__ __forceinline__ float f2sum(ull u) {
    float x, y;
    asm("mov.b64 {%0,%1}, %2;" : "=f"(x), "=f"(y) : "l"(u));
    return x + y;
}
__device__ __forceinline__ ull fpack(float lo, float hi) {
    ull p;
    asm("mov.b64 %0, {%1,%2};" : "=l"(p) : "f"(lo), "f"(hi));
    return p;
}

__device__ __forceinline__ float tanha(float x) {
    float y;
    asm("tanh.approx.f32 %0, %1;" : "=f"(y) : "f"(x));
    return y;
}
__device__ __forceinline__ float sigap(float x) {
    return fmaf(0.5f, tanha(0.5f * x), 0.5f);
}

// cp.async helpers
__device__ __forceinline__ void cp_async16(u32 saddr, const void* gaddr) {
    asm volatile("cp.async.cg.shared.global [%0], [%1], 16;" :: "r"(saddr), "l"(gaddr));
}
#define CP_COMMIT() asm volatile("cp.async.commit_group;" ::: "memory")
#define CP_WAIT1()  asm volatile("cp.async.wait_group 1;" ::: "memory")

// ============================================================================
// K1: dilated conv (k=3, dil=2, pad=2) + batchnorm(inference) + exact GELU
// ============================================================================
#define K1_TT 32
__global__ void k1_conv(const float* __restrict__ x, const float* __restrict__ mix_w,
                        const float* __restrict__ bn_g, const float* __restrict__ bn_b,
                        const float* __restrict__ bn_m, const float* __restrict__ bn_v)
{
    extern __shared__ float sm[];
    float* ws = sm;                    // [3][64][64] : ws[(k*64+i)*64+f]
    float* xs = sm + 3*64*64;          // [36][64]
    const int b  = blockIdx.y;
    const int t0 = blockIdx.x * K1_TT;
    const int tid = threadIdx.x;       // 256 threads

    for (int idx = tid; idx < FF*FF*3; idx += 256) {
        int f = idx / 192; int rem = idx - f*192; int i = rem / 3; int k = rem - i*3;
        ws[(k*64 + i)*64 + f] = mix_w[idx];
    }
    for (int idx = tid; idx < 36*64; idx += 256) {
        int r = idx >> 6; int i = idx & 63;
        int t = t0 - 2 + r;
        xs[idx] = (t >= 0 && t < TT) ? x[((b*TT) + t)*64 + i] : 0.f;
    }
    __syncthreads();

    const int f  = tid & 63;
    const int tg = tid >> 6;
    const float sc = bn_g[f] * rsqrtf(bn_v[f] + 1e-5f);
    const float sh = bn_b[f] - bn_m[f] * sc;
    const float4* xs4 = (const float4*)xs;

    for (int m = 0; m < 8; m++) {
        int tl = tg + 4*m;
        float acc = 0.f;
        #pragma unroll
        for (int k = 0; k < 3; k++) {
            int r = tl + 2*k;
            const float* wk = ws + k*4096 + f;
            #pragma unroll
            for (int i4 = 0; i4 < 16; i4++) {
                float4 xv = xs4[r*16 + i4];
                acc += xv.x * wk[(i4*4 + 0)*64];
                acc += xv.y * wk[(i4*4 + 1)*64];
                acc += xv.z * wk[(i4*4 + 2)*64];
                acc += xv.w * wk[(i4*4 + 3)*64];
            }
        }
        float y  = acc * sc + sh;
        float zz = 0.5f * y * (1.f + erff(y * 0.70710678118654752f));
        g_z[((b*TT) + (t0 + tl))*64 + f] = zz;
    }
}
#define SMEM1 ((3*64*64 + 36*64)*4)

// ============================================================================
// K2: xg1 = g_z @ w_ih1^T + b_ih1      [BT,64] @ [64,480]  — all-reg, f32x2
// ============================================================================
__global__ __launch_bounds__(480) void k2_xproj(const float* __restrict__ w_ih,
                                                const float* __restrict__ b_ih)
{
    extern __shared__ float zs[];      // [64][64]
    const int c = threadIdx.x;

    ull wr[32];
    #pragma unroll
    for (int i = 0; i < 16; i++) {
        ulonglong2 v = *reinterpret_cast<const ulonglong2*>(w_ih + c*64 + 4*i);
        wr[2*i] = v.x; wr[2*i+1] = v.y;
    }
    const float bias = b_ih[c];

    const int start = blockIdx.x * 896;          // 14 tiles of 64 rows
    for (int tile = 0; tile < 14; tile++) {
        int r0 = start + tile*64;
        if (r0 >= BT) break;
        __syncthreads();
        for (int idx = c; idx < 64*16; idx += 480)
            ((float4*)zs)[idx] = ((const float4*)(g_z + (size_t)r0*64))[idx];
        __syncthreads();
        for (int r = 0; r < 64; r += 2) {
            ull a0 = 0ull, a1 = 0ull, b0 = 0ull, b1 = 0ull;
            const float* z0 = zs + r*64;
            const float* z1 = zs + r*64 + 64;
            #pragma unroll
            for (int i = 0; i < 16; i++) {
                ulonglong2 h0 = *reinterpret_cast<const ulonglong2*>(z0 + 4*i);
                ulonglong2 h1 = *reinterpret_cast<const ulonglong2*>(z1 + 4*i);
                a0 = fma2(h0.x, wr[2*i],   a0);
                a1 = fma2(h0.y, wr[2*i+1], a1);
                b0 = fma2(h1.x, wr[2*i],   b0);
                b1 = fma2(h1.y, wr[2*i+1], b1);
            }
            g_xg1[(size_t)(r0 + r    )*GG + c] = bias + f2sum(a0) + f2sum(a1);
            g_xg1[(size_t)(r0 + r + 1)*GG + c] = bias + f2sum(b0) + f2sum(b1);
        }
    }
}
#define SMEM2 (64*64*4)

// ============================================================================
// K4: xg2 = g_h1 @ w_ih2^T + b_ih2     [BT,160] @ [160,480]
//     hybrid: k<80 in regs (f32x2), k>=80 in smem as ull pairs [q][480+1]
// ============================================================================
#define K4_WS 481
__global__ __launch_bounds__(480) void k4_xproj160(const float* __restrict__ w_ih,
                                                   const float* __restrict__ b_ih)
{
    extern __shared__ __align__(16) char smraw[];
    ull*   wsm = (ull*)smraw;                      // [40][481] k-pairs for k>=80
    float* zs  = (float*)(smraw + 40*K4_WS*8);     // [16][160]
    const int c = threadIdx.x;

    for (int idx = c; idx < 480*40; idx += 480) {
        int cc = idx / 40; int q = idx - cc*40;
        float lo = w_ih[cc*160 + 80 + 2*q];
        float hi = w_ih[cc*160 + 81 + 2*q];
        wsm[q*K4_WS + cc] = fpack(lo, hi);
    }
    ull wr[40];
    #pragma unroll
    for (int i = 0; i < 20; i++) {
        ulonglong2 v = *reinterpret_cast<const ulonglong2*>(w_ih + c*160 + 4*i);
        wr[2*i] = v.x; wr[2*i+1] = v.y;
    }
    const float bias = b_ih[c];

    const int start = blockIdx.x * 896;            // 56 tiles of 16 rows
    for (int tile = 0; tile < 56; tile++) {
        int r0 = start + tile*16;
        if (r0 >= BT) break;
        __syncthreads();
        for (int idx = c; idx < 16*40; idx += 480)
            ((float4*)zs)[idx] = ((const float4*)(g_h1 + (size_t)r0*160))[idx];
        __syncthreads();
        for (int rg = 0; rg < 16; rg += 4) {
            const float* z0 = zs + (rg+0)*160;
            const float* z1 = zs + (rg+1)*160;
            const float* z2 = zs + (rg+2)*160;
            const float* z3 = zs + (rg+3)*160;
            ull a0 = 0ull, a1 = 0ull, a2 = 0ull, a3 = 0ull;
            #pragma unroll
            for (int i = 0; i < 20; i++) {
                ull wa = wr[2*i], wb = wr[2*i+1];
                ulonglong2 h;
                h = *reinterpret_cast<const ulonglong2*>(z0 + 4*i);
                a0 = fma2(h.x, wa, a0); a0 = fma2(h.y, wb, a0);
                h = *reinterpret_cast<const ulonglong2*>(z1 + 4*i);
                a1 = fma2(h.x, wa, a1); a1 = fma2(h.y, wb, a1);
                h = *reinterpret_cast<const ulonglong2*>(z2 + 4*i);
                a2 = fma2(h.x, wa, a2); a2 = fma2(h.y, wb, a2);
                h = *reinterpret_cast<const ulonglong2*>(z3 + 4*i);
                a3 = fma2(h.x, wa, a3); a3 = fma2(h.y, wb, a3);
            }
            #pragma unroll
            for (int i = 0; i < 20; i++) {
                ull wa = wsm[(2*i  )*K4_WS + c];
                ull wb = wsm[(2*i+1)*K4_WS + c];
                ulonglong2 h;
                h = *reinterpret_cast<const ulonglong2*>(z0 + 80 + 4*i);
                a0 = fma2(h.x, wa, a0); a0 = fma2(h.y, wb, a0);
                h = *reinterpret_cast<const ulonglong2*>(z1 + 80 + 4*i);
                a1 = fma2(h.x, wa, a1); a1 = fma2(h.y, wb, a1);
                h = *reinterpret_cast<const ulonglong2*>(z2 + 80 + 4*i);
                a2 = fma2(h.x, wa, a2); a2 = fma2(h.y, wb, a2);
                h = *reinterpret_cast<const ulonglong2*>(z3 + 80 + 4*i);
                a3 = fma2(h.x, wa, a3); a3 = fma2(h.y, wb, a3);
            }
            g_xg2[(size_t)(r0 + rg    )*GG + c] = bias + f2sum(a0);
            g_xg2[(size_t)(r0 + rg + 1)*GG + c] = bias + f2sum(a1);
            g_xg2[(size_t)(r0 + rg + 2)*GG + c] = bias + f2sum(a2);
            g_xg2[(size_t)(r0 + rg + 3)*GG + c] = bias + f2sum(a3);
        }
    }
}
#define SMEM4 (40*K4_WS*8 + 16*160*4)

// ============================================================================
// K3: GRU via tensor cores, v2. 16 batches per CTA, grid=4.
//     W-fragments in REGISTERS (80 u32/thread, loaded once).
//     xg staged via cp.async into double-buffered smem (no reg prefetch).
//     Per step: hp[16,480] = h16[16,160] @ W^T via mma.sync m16n8k16 (f32 acc).
// ============================================================================
#define NB   16            // batches per CTA
#define WST  168           // fp16 row stride (h16) -> conflict-free A reads
#define HPS  482           // hp row stride (f32)
#define XS   480           // xg stage row stride (f32)
#define OFF_H16 0
#define OFF_HP  (OFF_H16 + NB*WST*2)       // 5376
#define OFF_H32 (OFF_HP + NB*HPS*4)        // 36224
#define OFF_XS  (OFF_H32 + NB*HH*4)        // 46464
#define SMEMG   (OFF_XS + 2*NB*XS*4)       // 107904 B < 227KB

__device__ __forceinline__ void mma16816(float c[4], u32 a0, u32 a1, u32 a2, u32 a3,
                                         u32 b0, u32 b1) {
    asm("mma.sync.aligned.m16n8k16.row.col.f32.f16.f16.f32 "
        "{%0,%1,%2,%3}, {%4,%5,%6,%7}, {%8,%9}, {%0,%1,%2,%3};"
        : "+f"(c[0]), "+f"(c[1]), "+f"(c[2]), "+f"(c[3])
        : "r"(a0), "r"(a1), "r"(a2), "r"(a3), "r"(b0), "r"(b1));
}

__global__ __launch_bounds__(480, 1) void k_gru_mma(const float* __restrict__ w_hh,
                                                    const float* __restrict__ b_hh,
                                                    int which)
{
    extern __shared__ __align__(16) char smg[];
    __half* h16 = (__half*)(smg + OFF_H16);   // [16][WST]
    float*  hp  = (float*) (smg + OFF_HP);    // [16][HPS]
    float*  h32 = (float*) (smg + OFF_H32);   // [16][160]
    float*  xs  = (float*) (smg + OFF_XS);    // [2][16][480]

    const int tid = threadIdx.x;
    const int b0  = blockIdx.x * NB;
    const int w    = tid >> 5;
    const int l    = tid & 31;
    const int grp  = l >> 2;        // 0..7
    const int tid4 = l & 3;         // 0..3
    const int n0w  = w * 32;

    // ---- W fragments -> registers (one-time, fp32 -> fp16x2) ----
    u32 wf[4][10][2];
    #pragma unroll
    for (int sub = 0; sub < 4; sub++) {
        const int nr = n0w + sub*8 + grp;
        #pragma unroll
        for (int kc = 0; kc < 10; kc++) {
            const int k0 = kc*16 + 2*tid4;
            float2 lo = *reinterpret_cast<const float2*>(&w_hh[nr*160 + k0]);
            float2 hi = *reinterpret_cast<const float2*>(&w_hh[nr*160 + k0 + 8]);
            __half2 hlo = __floats2half2_rn(lo.x, lo.y);
            __half2 hhi = __floats2half2_rn(hi.x, hi.y);
            wf[sub][kc][0] = *reinterpret_cast<u32*>(&hlo);
            wf[sub][kc][1] = *reinterpret_cast<u32*>(&hhi);
        }
    }

    // gate-thread mapping: unit ui, batches q = q0 + 3j (clamped)
    const int ui = tid % HH;
    const int q0 = tid / HH;        // 0..2
    const float bbr = b_hh[ui];
    const float bbz = b_hh[HH + ui];
    const float bbn = b_hh[2*HH + ui];

    for (int idx = tid; idx < NB*WST; idx += 480) h16[idx] = __float2half(0.f);
    for (int idx = tid; idx < NB*HH;  idx += 480) h32[idx] = 0.f;

    const float* __restrict__ xg = which ? g_xg2 : g_xg1;

    // prologue: stage xg(t=0) into xs buf 0
    #pragma unroll
    for (int i = 0; i < 4; i++) {
        int idx4 = tid + 480*i;                  // 0..1919
        int q = idx4 / 120, c4 = idx4 - q*120;
        u32 s = (u32)__cvta_generic_to_shared(&xs[q*XS + c4*4]);
        cp_async16(s, xg + (size_t)(b0+q)*TT*GG + c4*4);
    }
    CP_COMMIT();
    __syncthreads();

    for (int t = 0; t < TT; t++) {
        // stage xg(t+1) into the other buffer (overlaps MMA + gates)
        {
            const int tn = (t+1 < TT) ? (t+1) : (TT-1);
            const int bufn = (t+1) & 1;
            #pragma unroll
            for (int i = 0; i < 4; i++) {
                int idx4 = tid + 480*i;
                int q = idx4 / 120, c4 = idx4 - q*120;
                u32 s = (u32)__cvta_generic_to_shared(&xs[(bufn*NB + q)*XS + c4*4]);
                cp_async16(s, xg + ((size_t)(b0+q)*TT + tn)*GG + c4*4);
            }
            CP_COMMIT();
        }

        // ---------------- MMA phase: hp = h16 @ W^T ----------------
        float c0[4], c1[4], c2[4], c3[4];
        #pragma unroll
        for (int k = 0; k < 4; k++) { c0[k]=0.f; c1[k]=0.f; c2[k]=0.f; c3[k]=0.f; }

        #pragma unroll
        for (int kc = 0; kc < 10; kc++) {
            const int kb = kc*16 + 2*tid4;
            u32 a0 = *(const u32*)&h16[(grp    )*WST + kb    ];
            u32 a1 = *(const u32*)&h16[(grp + 8)*WST + kb    ];
            u32 a2 = *(const u32*)&h16[(grp    )*WST + kb + 8];
            u32 a3 = *(const u32*)&h16[(grp + 8)*WST + kb + 8];
            mma16816(c0, a0,a1,a2,a3, wf[0][kc][0], wf[0][kc][1]);
            mma16816(c1, a0,a1,a2,a3, wf[1][kc][0], wf[1][kc][1]);
            mma16816(c2, a0,a1,a2,a3, wf[2][kc][0], wf[2][kc][1]);
            mma16816(c3, a0,a1,a2,a3, wf[3][kc][0], wf[3][kc][1]);
        }
        // store D frags -> hp
        {
            int col0 = n0w + 0*8 + 2*tid4;
            *(float2*)&hp[(grp  )*HPS + col0] = make_float2(c0[0], c0[1]);
            *(float2*)&hp[(grp+8)*HPS + col0] = make_float2(c0[2], c0[3]);
            int col1 = n0w + 1*8 + 2*tid4;
            *(float2*)&hp[(grp  )*HPS + col1] = make_float2(c1[0], c1[1]);
            *(float2*)&hp[(grp+8)*HPS + col1] = make_float2(c1[2], c1[3]);
            int col2 = n0w + 2*8 + 2*tid4;
            *(float2*)&hp[(grp  )*HPS + col2] = make_float2(c2[0], c2[1]);
            *(float2*)&hp[(grp+8)*HPS + col2] = make_float2(c2[2], c2[3]);
            int col3 = n0w + 3*8 + 2*tid4;
            *(float2*)&hp[(grp  )*HPS + col3] = make_float2(c3[0], c3[1]);
            *(float2*)&hp[(grp+8)*HPS + col3] = make_float2(c3[2], c3[3]);
        }
        CP_WAIT1();           // xg(t) staged (newest group = t+1 may still fly)
        __syncthreads();

        // ---------------- gate phase ----------------
        const float* xb = &xs[(t & 1) * NB * XS];
        #pragma unroll
        for (int j = 0; j < 6; j++) {
            int q = q0 + 3*j;
            bool valid = (q < NB);
            int qc = valid ? q : NB-1;
            float xr = xb[qc*XS + ui];
            float xz = xb[qc*XS + HH + ui];
            float xn = xb[qc*XS + 2*HH + ui];
            float hpr = hp[qc*HPS + ui];
            float hpz = hp[qc*HPS + HH + ui];
            float hpn = hp[qc*HPS + 2*HH + ui];
            float r  = sigap(xr + bbr + hpr);
            float z  = sigap(xz + bbz + hpz);
            float nn = tanha(xn + r * (hpn + bbn));
            float hold = h32[qc*HH + ui];
            float hnew = (1.f - z) * nn + z * hold;
            if (valid) {
                h32[qc*HH + ui] = hnew;
                h16[qc*WST + ui] = __float2half(hnew);
                if (!which) g_h1[((size_t)(b0 + qc)*TT + t)*HH + ui] = hnew;
            }
        }
        __syncthreads();
    }

    if (which) {
        for (int idx = tid; idx < NB*HH; idx += 480)
            g_h2T[(b0 + idx/HH)*HH + (idx % HH)] = h32[idx];
    }
}

// ============================================================================
// K5: head
// ============================================================================
__global__ void k_head(const float* __restrict__ hw1, const float* __restrict__ hb1,
                       const float* __restrict__ hw2, const float* __restrict__ hb2,
                       float* __restrict__ out)
{
    __shared__ float q[80];
    const int b = blockIdx.x;
    const int j = threadIdx.x;
    const float* h = g_h2T + b*HH;
    if (j < 80) {
        float acc = hb1[j];
        #pragma unroll 4
        for (int k = 0; k < 160; k++) acc += h[k] * hw1[j*160 + k];
        q[j] = 0.5f * acc * (1.f + erff(acc * 0.70710678118654752f));
    }
    __syncthreads();
    if (j < 2) {
        float o = hb2[j];
        #pragma unroll 4
        for (int k = 0; k < 80; k++) o += q[k] * hw2[j*80 + k];
        out[b*2 + j] = o;
    }
}

// ============================================================================
extern "C" void kernel_launch(void* const* d_in, const int* in_sizes, int n_in,
                              void* d_out, int out_size)
{
    const float* x     = (const float*)d_in[0];
    const float* mix_w = (const float*)d_in[1];
    const float* bn_g  = (const float*)d_in[2];
    const float* bn_b  = (const float*)d_in[3];
    const float* bn_m  = (const float*)d_in[4];
    const float* bn_v  = (const float*)d_in[5];
    const float* w_ih1 = (const float*)d_in[6];
    const float* w_hh1 = (const float*)d_in[7];
    const float* b_ih1 = (const float*)d_in[8];
    const float* b_hh1 = (const float*)d_in[9];
    const float* w_ih2 = (const float*)d_in[10];
    const float* w_hh2 = (const float*)d_in[11];
    const float* b_ih2 = (const float*)d_in[12];
    const float* b_hh2 = (const float*)d_in[13];
    const float* hw1   = (const float*)d_in[14];
    const float* hb1   = (const float*)d_in[15];
    const float* hw2   = (const float*)d_in[16];
    const float* hb2   = (const float*)d_in[17];
    float* out = (float*)d_out;

    cudaFuncSetAttribute(k1_conv,     cudaFuncAttributeMaxDynamicSharedMemorySize, SMEM1);
    cudaFuncSetAttribute(k2_xproj,    cudaFuncAttributeMaxDynamicSharedMemorySize, SMEM2);
    cudaFuncSetAttribute(k4_xproj160, cudaFuncAttributeMaxDynamicSharedMemorySize, SMEM4);
    cudaFuncSetAttribute(k_gru_mma,   cudaFuncAttributeMaxDynamicSharedMemorySize, SMEMG);

    k1_conv<<<dim3(TT/K1_TT, BB), 256, SMEM1>>>(x, mix_w, bn_g, bn_b, bn_m, bn_v);
    k2_xproj<<<148, 480, SMEM2>>>(w_ih1, b_ih1);
    k_gru_mma<<<BB/NB, 480, SMEMG>>>(w_hh1, b_hh1, 0);
    k4_xproj160<<<148, 480, SMEM4>>>(w_ih2, b_ih2);
    k_gru_mma<<<BB/NB, 480, SMEMG>>>(w_hh2, b_hh2, 1);
    k_head<<<BB, 128>>>(hw1, hb1, hw2, hb2, out);
}

// round 17
// speedup vs baseline: 1.4113x; 1.1617x over previous
#include <cuda_runtime.h>
#include <cuda_fp16.h>
#include <stdint.h>
#include <math.h>

#define BB 64
#define TT 2048
#define FF 64
#define HH 160
#define GG 480            // 3*H
#define BT (BB*TT)        // 131072

typedef unsigned long long ull;
typedef unsigned int u32;
typedef unsigned short u16;

// ---------------- scratch (device globals; allocation-free) ----------------
__device__ float g_z  [BT*FF];
__device__ float g_xg1[BT*GG];
__device__ float g_h1 [BT*HH];
__device__ float g_xg2[BT*GG];
__device__ float g_h2T[BB*HH];

// ---------------- packed f32x2 helpers (K2/K4 only) ----------------
__device__ __forceinline__ ull fma2(ull a, ull b, ull c) {
    ull d;
    asm("fma.rn.f32x2 %0, %1, %2, %3;" : "=l"(d) : "l"(a), "l"(b), "l"(c));
    return d;
}
__device__ __forceinline__ float f2sum(ull u) {
    float x, y;
    asm("mov.b64 {%0,%1}, %2;" : "=f"(x), "=f"(y) : "l"(u));
    return x + y;
}
__device__ __forceinline__ ull fpack(float lo, float hi) {
    ull p;
    asm("mov.b64 %0, {%1,%2};" : "=l"(p) : "f"(lo), "f"(hi));
    return p;
}

__device__ __forceinline__ float tanha(float x) {
    float y;
    asm("tanh.approx.f32 %0, %1;" : "=f"(y) : "f"(x));
    return y;
}
__device__ __forceinline__ float sigap(float x) {
    return fmaf(0.5f, tanha(0.5f * x), 0.5f);
}

// cp.async helpers
__device__ __forceinline__ void cp_async16(u32 saddr, const void* gaddr) {
    asm volatile("cp.async.cg.shared.global [%0], [%1], 16;" :: "r"(saddr), "l"(gaddr));
}
#define CP_COMMIT() asm volatile("cp.async.commit_group;" ::: "memory")
#define CP_WAIT1()  asm volatile("cp.async.wait_group 1;" ::: "memory")

// ============================================================================
// K1: dilated conv (k=3, dil=2, pad=2) + batchnorm(inference) + exact GELU
// ============================================================================
#define K1_TT 32
__global__ void k1_conv(const float* __restrict__ x, const float* __restrict__ mix_w,
                        const float* __restrict__ bn_g, const float* __restrict__ bn_b,
                        const float* __restrict__ bn_m, const float* __restrict__ bn_v)
{
    extern __shared__ float sm[];
    float* ws = sm;                    // [3][64][64]
    float* xs = sm + 3*64*64;          // [36][64]
    const int b  = blockIdx.y;
    const int t0 = blockIdx.x * K1_TT;
    const int tid = threadIdx.x;       // 256 threads

    for (int idx = tid; idx < FF*FF*3; idx += 256) {
        int f = idx / 192; int rem = idx - f*192; int i = rem / 3; int k = rem - i*3;
        ws[(k*64 + i)*64 + f] = mix_w[idx];
    }
    for (int idx = tid; idx < 36*64; idx += 256) {
        int r = idx >> 6; int i = idx & 63;
        int t = t0 - 2 + r;
        xs[idx] = (t >= 0 && t < TT) ? x[((b*TT) + t)*64 + i] : 0.f;
    }
    __syncthreads();

    const int f  = tid & 63;
    const int tg = tid >> 6;
    const float sc = bn_g[f] * rsqrtf(bn_v[f] + 1e-5f);
    const float sh = bn_b[f] - bn_m[f] * sc;
    const float4* xs4 = (const float4*)xs;

    for (int m = 0; m < 8; m++) {
        int tl = tg + 4*m;
        float acc = 0.f;
        #pragma unroll
        for (int k = 0; k < 3; k++) {
            int r = tl + 2*k;
            const float* wk = ws + k*4096 + f;
            #pragma unroll
            for (int i4 = 0; i4 < 16; i4++) {
                float4 xv = xs4[r*16 + i4];
                acc += xv.x * wk[(i4*4 + 0)*64];
                acc += xv.y * wk[(i4*4 + 1)*64];
                acc += xv.z * wk[(i4*4 + 2)*64];
                acc += xv.w * wk[(i4*4 + 3)*64];
            }
        }
        float y  = acc * sc + sh;
        float zz = 0.5f * y * (1.f + erff(y * 0.70710678118654752f));
        g_z[((b*TT) + (t0 + tl))*64 + f] = zz;
    }
}
#define SMEM1 ((3*64*64 + 36*64)*4)

// ============================================================================
// K2: xg1 = g_z @ w_ih1^T + b_ih1      [BT,64] @ [64,480]  — all-reg, f32x2
// ============================================================================
__global__ __launch_bounds__(480) void k2_xproj(const float* __restrict__ w_ih,
                                                const float* __restrict__ b_ih)
{
    extern __shared__ float zs[];      // [64][64]
    const int c = threadIdx.x;

    ull wr[32];
    #pragma unroll
    for (int i = 0; i < 16; i++) {
        ulonglong2 v = *reinterpret_cast<const ulonglong2*>(w_ih + c*64 + 4*i);
        wr[2*i] = v.x; wr[2*i+1] = v.y;
    }
    const float bias = b_ih[c];

    const int start = blockIdx.x * 896;
    for (int tile = 0; tile < 14; tile++) {
        int r0 = start + tile*64;
        if (r0 >= BT) break;
        __syncthreads();
        for (int idx = c; idx < 64*16; idx += 480)
            ((float4*)zs)[idx] = ((const float4*)(g_z + (size_t)r0*64))[idx];
        __syncthreads();
        for (int r = 0; r < 64; r += 2) {
            ull a0 = 0ull, a1 = 0ull, b0 = 0ull, b1 = 0ull;
            const float* z0 = zs + r*64;
            const float* z1 = zs + r*64 + 64;
            #pragma unroll
            for (int i = 0; i < 16; i++) {
                ulonglong2 h0 = *reinterpret_cast<const ulonglong2*>(z0 + 4*i);
                ulonglong2 h1 = *reinterpret_cast<const ulonglong2*>(z1 + 4*i);
                a0 = fma2(h0.x, wr[2*i],   a0);
                a1 = fma2(h0.y, wr[2*i+1], a1);
                b0 = fma2(h1.x, wr[2*i],   b0);
                b1 = fma2(h1.y, wr[2*i+1], b1);
            }
            g_xg1[(size_t)(r0 + r    )*GG + c] = bias + f2sum(a0) + f2sum(a1);
            g_xg1[(size_t)(r0 + r + 1)*GG + c] = bias + f2sum(b0) + f2sum(b1);
        }
    }
}
#define SMEM2 (64*64*4)

// ============================================================================
// K4: xg2 = g_h1 @ w_ih2^T + b_ih2     [BT,160] @ [160,480]
// ============================================================================
#define K4_WS 481
__global__ __launch_bounds__(480) void k4_xproj160(const float* __restrict__ w_ih,
                                                   const float* __restrict__ b_ih)
{
    extern __shared__ __align__(16) char smraw[];
    ull*   wsm = (ull*)smraw;                      // [40][481]
    float* zs  = (float*)(smraw + 40*K4_WS*8);     // [16][160]
    const int c = threadIdx.x;

    for (int idx = c; idx < 480*40; idx += 480) {
        int cc = idx / 40; int q = idx - cc*40;
        float lo = w_ih[cc*160 + 80 + 2*q];
        float hi = w_ih[cc*160 + 81 + 2*q];
        wsm[q*K4_WS + cc] = fpack(lo, hi);
    }
    ull wr[40];
    #pragma unroll
    for (int i = 0; i < 20; i++) {
        ulonglong2 v = *reinterpret_cast<const ulonglong2*>(w_ih + c*160 + 4*i);
        wr[2*i] = v.x; wr[2*i+1] = v.y;
    }
    const float bias = b_ih[c];

    const int start = blockIdx.x * 896;
    for (int tile = 0; tile < 56; tile++) {
        int r0 = start + tile*16;
        if (r0 >= BT) break;
        __syncthreads();
        for (int idx = c; idx < 16*40; idx += 480)
            ((float4*)zs)[idx] = ((const float4*)(g_h1 + (size_t)r0*160))[idx];
        __syncthreads();
        for (int rg = 0; rg < 16; rg += 4) {
            const float* z0 = zs + (rg+0)*160;
            const float* z1 = zs + (rg+1)*160;
            const float* z2 = zs + (rg+2)*160;
            const float* z3 = zs + (rg+3)*160;
            ull a0 = 0ull, a1 = 0ull, a2 = 0ull, a3 = 0ull;
            #pragma unroll
            for (int i = 0; i < 20; i++) {
                ull wa = wr[2*i], wb = wr[2*i+1];
                ulonglong2 h;
                h = *reinterpret_cast<const ulonglong2*>(z0 + 4*i);
                a0 = fma2(h.x, wa, a0); a0 = fma2(h.y, wb, a0);
                h = *reinterpret_cast<const ulonglong2*>(z1 + 4*i);
                a1 = fma2(h.x, wa, a1); a1 = fma2(h.y, wb, a1);
                h = *reinterpret_cast<const ulonglong2*>(z2 + 4*i);
                a2 = fma2(h.x, wa, a2); a2 = fma2(h.y, wb, a2);
                h = *reinterpret_cast<const ulonglong2*>(z3 + 4*i);
                a3 = fma2(h.x, wa, a3); a3 = fma2(h.y, wb, a3);
            }
            #pragma unroll
            for (int i = 0; i < 20; i++) {
                ull wa = wsm[(2*i  )*K4_WS + c];
                ull wb = wsm[(2*i+1)*K4_WS + c];
                ulonglong2 h;
                h = *reinterpret_cast<const ulonglong2*>(z0 + 80 + 4*i);
                a0 = fma2(h.x, wa, a0); a0 = fma2(h.y, wb, a0);
                h = *reinterpret_cast<const ulonglong2*>(z1 + 80 + 4*i);
                a1 = fma2(h.x, wa, a1); a1 = fma2(h.y, wb, a1);
                h = *reinterpret_cast<const ulonglong2*>(z2 + 80 + 4*i);
                a2 = fma2(h.x, wa, a2); a2 = fma2(h.y, wb, a2);
                h = *reinterpret_cast<const ulonglong2*>(z3 + 80 + 4*i);
                a3 = fma2(h.x, wa, a3); a3 = fma2(h.y, wb, a3);
            }
            g_xg2[(size_t)(r0 + rg    )*GG + c] = bias + f2sum(a0);
            g_xg2[(size_t)(r0 + rg + 1)*GG + c] = bias + f2sum(a1);
            g_xg2[(size_t)(r0 + rg + 2)*GG + c] = bias + f2sum(a2);
            g_xg2[(size_t)(r0 + rg + 3)*GG + c] = bias + f2sum(a3);
        }
    }
}
#define SMEM4 (40*K4_WS*8 + 16*160*4)

// ============================================================================
// K3: GRU via tensor cores, cluster-2 N-split. 4 clusters x 2 CTAs, 16 batch/cluster.
//     CTA rank owns units U=[80r, 80r+80): its 240 n-cols = r/z/n rows of U
//     -> gates fully CTA-local. Only hnew (16x80 fp16) is pushed to the peer.
//     W-frags in registers; h16 double-buffered (CTA skew safety);
//     xg slice staged by cp.async (double-buffered); 1 cluster barrier/step.
// ============================================================================
#define NB    16
#define NCL   240          // local n-cols per CTA
#define WST   168          // h16 row stride (halves)
#define HPS2  242          // hp row stride (f32)
#define XSS   240          // xs row stride (f32)
#define OFF_H16G 0                                  // [2][16][WST] fp16
#define OFF_HPG  (OFF_H16G + 2*NB*WST*2)            // [16][HPS2] f32
#define OFF_H32G (OFF_HPG + NB*HPS2*4)              // [16][80] f32
#define OFF_XSG  (OFF_H32G + NB*80*4)               // [2][16][XSS] f32
#define SMEMG    (OFF_XSG + 2*NB*XSS*4)             // ~57 KB

__device__ __forceinline__ void mma16816(float c[4], u32 a0, u32 a1, u32 a2, u32 a3,
                                         u32 b0, u32 b1) {
    asm("mma.sync.aligned.m16n8k16.row.col.f32.f16.f16.f32 "
        "{%0,%1,%2,%3}, {%4,%5,%6,%7}, {%8,%9}, {%0,%1,%2,%3};"
        : "+f"(c[0]), "+f"(c[1]), "+f"(c[2]), "+f"(c[3])
        : "r"(a0), "r"(a1), "r"(a2), "r"(a3), "r"(b0), "r"(b1));
}

__global__ __launch_bounds__(480, 1) void k_gru_mma(const float* __restrict__ w_hh,
                                                    const float* __restrict__ b_hh,
                                                    int which)
{
    extern __shared__ __align__(16) char smg[];
    __half* h16 = (__half*)(smg + OFF_H16G);  // [2][16][WST]
    float*  hp  = (float*) (smg + OFF_HPG);   // [16][HPS2]
    float*  h32 = (float*) (smg + OFF_H32G);  // [16][80]
    float*  xs  = (float*) (smg + OFF_XSG);   // [2][16][XSS]

    const int tid = threadIdx.x;
    u32 rank;
    asm("mov.u32 %0, %%cluster_ctarank;" : "=r"(rank));
    const int b0 = (blockIdx.x >> 1) * NB;    // cluster id * NB
    const int u0 = rank * 80;                 // first owned unit

    const int w    = tid >> 5;
    const int l    = tid & 31;
    const int grp  = l >> 2;
    const int tid4 = l & 3;
    const int n0w  = w * 16;                  // local col base (2 subtiles)

    // ---- W fragments -> registers (local col -> global gate row) ----
    u32 wf[2][10][2];
    #pragma unroll
    for (int sub = 0; sub < 2; sub++) {
        const int cl = n0w + sub*8 + grp;              // local col 0..239
        const int G  = (cl / 80) * 160 + u0 + (cl % 80);
        #pragma unroll
        for (int kc = 0; kc < 10; kc++) {
            const int k0 = kc*16 + 2*tid4;
            float2 lo = *reinterpret_cast<const float2*>(&w_hh[G*160 + k0]);
            float2 hi = *reinterpret_cast<const float2*>(&w_hh[G*160 + k0 + 8]);
            __half2 hlo = __floats2half2_rn(lo.x, lo.y);
            __half2 hhi = __floats2half2_rn(hi.x, hi.y);
            wf[sub][kc][0] = *reinterpret_cast<u32*>(&hlo);
            wf[sub][kc][1] = *reinterpret_cast<u32*>(&hhi);
        }
    }

    // peer h16 base (DSMEM)
    u32 ls = (u32)__cvta_generic_to_shared(h16);
    u32 rs;
    asm("mapa.shared::cluster.u32 %0, %1, %2;" : "=r"(rs) : "r"(ls), "r"(rank ^ 1u));

    for (int idx = tid; idx < 2*NB*WST; idx += 480) h16[idx] = __float2half(0.f);
    for (int idx = tid; idx < NB*80;   idx += 480) h32[idx] = 0.f;

    const float* __restrict__ xg = which ? g_xg2 : g_xg1;

    // prologue: stage xg(t=0) slice into xs buf 0
    // 960 chunks of 16B: idx -> q=idx/60, blk=(idx%60)/20, off=idx%20
    #pragma unroll
    for (int i = 0; i < 2; i++) {
        int idx = tid + 480*i;
        int q = idx / 60; int rmn = idx - q*60; int blk = rmn / 20; int off = rmn - blk*20;
        u32 s = (u32)__cvta_generic_to_shared(&xs[q*XSS + blk*80 + off*4]);
        cp_async16(s, xg + (size_t)(b0+q)*TT*GG + blk*160 + u0 + off*4);
    }
    CP_COMMIT();
    __syncthreads();
    asm volatile("barrier.cluster.arrive.aligned;" ::: "memory");
    asm volatile("barrier.cluster.wait.aligned;"   ::: "memory");

    for (int t = 0; t < TT; t++) {
        const int buf = t & 1;

        // stage xg(t+1)
        {
            const int tn = (t+1 < TT) ? (t+1) : (TT-1);
            const int bufn = (t+1) & 1;
            #pragma unroll
            for (int i = 0; i < 2; i++) {
                int idx = tid + 480*i;
                int q = idx / 60; int rmn = idx - q*60; int blk = rmn / 20; int off = rmn - blk*20;
                u32 s = (u32)__cvta_generic_to_shared(&xs[(bufn*NB + q)*XSS + blk*80 + off*4]);
                cp_async16(s, xg + ((size_t)(b0+q)*TT + tn)*GG + blk*160 + u0 + off*4);
            }
            CP_COMMIT();
        }

        // ---------------- MMA: hp[16][240] = h16 @ Wlocal^T ----------------
        float c0[4], c1[4];
        #pragma unroll
        for (int k = 0; k < 4; k++) { c0[k]=0.f; c1[k]=0.f; }
        const __half* hb = &h16[buf*NB*WST];
        #pragma unroll
        for (int kc = 0; kc < 10; kc++) {
            const int kb = kc*16 + 2*tid4;
            u32 a0 = *(const u32*)&hb[(grp    )*WST + kb    ];
            u32 a1 = *(const u32*)&hb[(grp + 8)*WST + kb    ];
            u32 a2 = *(const u32*)&hb[(grp    )*WST + kb + 8];
            u32 a3 = *(const u32*)&hb[(grp + 8)*WST + kb + 8];
            mma16816(c0, a0,a1,a2,a3, wf[0][kc][0], wf[0][kc][1]);
            mma16816(c1, a0,a1,a2,a3, wf[1][kc][0], wf[1][kc][1]);
        }
        {
            int col0 = n0w + 2*tid4;
            *(float2*)&hp[(grp  )*HPS2 + col0] = make_float2(c0[0], c0[1]);
            *(float2*)&hp[(grp+8)*HPS2 + col0] = make_float2(c0[2], c0[3]);
            int col1 = n0w + 8 + 2*tid4;
            *(float2*)&hp[(grp  )*HPS2 + col1] = make_float2(c1[0], c1[1]);
            *(float2*)&hp[(grp+8)*HPS2 + col1] = make_float2(c1[2], c1[3]);
        }
        CP_WAIT1();
        __syncthreads();

        // ---------------- gates (own 80 units x 16 batches) ----------------
        const float* xb = &xs[(t & 1) * NB * XSS];
        const int nbuf = buf ^ 1;
        #pragma unroll
        for (int j = 0; j < 3; j++) {
            int idx = tid + 480*j;
            if (idx < NB*80) {
                int q  = idx / 80;
                int ui = idx - q*80;
                float xr = xb[q*XSS + ui];
                float xz = xb[q*XSS + 80 + ui];
                float xn = xb[q*XSS + 160 + ui];
                float hpr = hp[q*HPS2 + ui];
                float hpz = hp[q*HPS2 + 80 + ui];
                float hpn = hp[q*HPS2 + 160 + ui];
                float br = b_hh[u0 + ui];
                float bz = b_hh[160 + u0 + ui];
                float bn = b_hh[320 + u0 + ui];
                float r  = sigap(xr + br + hpr);
                float z  = sigap(xz + bz + hpz);
                float nn = tanha(xn + r * (hpn + bn));
                float hold = h32[q*80 + ui];
                float hnew = (1.f - z) * nn + z * hold;
                h32[q*80 + ui] = hnew;
                __half hh = __float2half(hnew);
                h16[(nbuf*NB + q)*WST + u0 + ui] = hh;                     // local
                u32 ra = rs + (u32)(((nbuf*NB + q)*WST + u0 + ui) * 2);    // peer
                asm volatile("st.shared::cluster.b16 [%0], %1;"
                             :: "r"(ra), "h"(*reinterpret_cast<u16*>(&hh)) : "memory");
                if (!which) g_h1[((size_t)(b0 + q)*TT + t)*HH + u0 + ui] = hnew;
            }
        }

        asm volatile("barrier.cluster.arrive.aligned;" ::: "memory");
        asm volatile("barrier.cluster.wait.aligned;"   ::: "memory");
    }

    if (which) {
        for (int idx = tid; idx < NB*80; idx += 480) {
            int q = idx / 80; int ui = idx - q*80;
            g_h2T[(b0 + q)*HH + u0 + ui] = h32[q*80 + ui];
        }
    }
}

// ============================================================================
// K5: head
// ============================================================================
__global__ void k_head(const float* __restrict__ hw1, const float* __restrict__ hb1,
                       const float* __restrict__ hw2, const float* __restrict__ hb2,
                       float* __restrict__ out)
{
    __shared__ float q[80];
    const int b = blockIdx.x;
    const int j = threadIdx.x;
    const float* h = g_h2T + b*HH;
    if (j < 80) {
        float acc = hb1[j];
        #pragma unroll 4
        for (int k = 0; k < 160; k++) acc += h[k] * hw1[j*160 + k];
        q[j] = 0.5f * acc * (1.f + erff(acc * 0.70710678118654752f));
    }
    __syncthreads();
    if (j < 2) {
        float o = hb2[j];
        #pragma unroll 4
        for (int k = 0; k < 80; k++) o += q[k] * hw2[j*80 + k];
        out[b*2 + j] = o;
    }
}

// ============================================================================
static void launch_gru(const float* w_hh, const float* b_hh, int which)
{
    cudaLaunchConfig_t cfg = {};
    cfg.gridDim  = dim3(2 * (BB / NB), 1, 1);   // 8 CTAs = 4 clusters
    cfg.blockDim = dim3(480, 1, 1);
    cfg.dynamicSmemBytes = SMEMG;
    cfg.stream = 0;
    cudaLaunchAttribute attrs[1];
    attrs[0].id = cudaLaunchAttributeClusterDimension;
    attrs[0].val.clusterDim.x = 2;
    attrs[0].val.clusterDim.y = 1;
    attrs[0].val.clusterDim.z = 1;
    cfg.attrs = attrs;
    cfg.numAttrs = 1;
    cudaLaunchKernelEx(&cfg, k_gru_mma, w_hh, b_hh, which);
}

extern "C" void kernel_launch(void* const* d_in, const int* in_sizes, int n_in,
                              void* d_out, int out_size)
{
    const float* x     = (const float*)d_in[0];
    const float* mix_w = (const float*)d_in[1];
    const float* bn_g  = (const float*)d_in[2];
    const float* bn_b  = (const float*)d_in[3];
    const float* bn_m  = (const float*)d_in[4];
    const float* bn_v  = (const float*)d_in[5];
    const float* w_ih1 = (const float*)d_in[6];
    const float* w_hh1 = (const float*)d_in[7];
    const float* b_ih1 = (const float*)d_in[8];
    const float* b_hh1 = (const float*)d_in[9];
    const float* w_ih2 = (const float*)d_in[10];
    const float* w_hh2 = (const float*)d_in[11];
    const float* b_ih2 = (const float*)d_in[12];
    const float* b_hh2 = (const float*)d_in[13];
    const float* hw1   = (const float*)d_in[14];
    const float* hb1   = (const float*)d_in[15];
    const float* hw2   = (const float*)d_in[16];
    const float* hb2   = (const float*)d_in[17];
    float* out = (float*)d_out;

    cudaFuncSetAttribute(k1_conv,     cudaFuncAttributeMaxDynamicSharedMemorySize, SMEM1);
    cudaFuncSetAttribute(k2_xproj,    cudaFuncAttributeMaxDynamicSharedMemorySize, SMEM2);
    cudaFuncSetAttribute(k4_xproj160, cudaFuncAttributeMaxDynamicSharedMemorySize, SMEM4);
    cudaFuncSetAttribute(k_gru_mma,   cudaFuncAttributeMaxDynamicSharedMemorySize, SMEMG);

    k1_conv<<<dim3(TT/K1_TT, BB), 256, SMEM1>>>(x, mix_w, bn_g, bn_b, bn_m, bn_v);
    k2_xproj<<<148, 480, SMEM2>>>(w_ih1, b_ih1);
    launch_gru(w_hh1, b_hh1, 0);
    k4_xproj160<<<148, 480, SMEM4>>>(w_ih2, b_ih2);
    launch_gru(w_hh2, b_hh2, 1);
    k_head<<<BB, 128>>>(hw1, hb1, hw2, hb2, out);
}